// round 6
// baseline (speedup 1.0000x reference)
#include <cuda_runtime.h>
#include <cuda_fp16.h>
#include <cstdint>

// ---------------- problem constants ----------------
#define C_TOT   2048
#define L_TOT   9
#define K_TOT   (C_TOT * L_TOT)     // 18432
#define NPIX    4096
#define O_TOT   256

// ---------------- GEMM tiling ----------------
#define N_TILE   64
#define M_TILE   128
#define K_CHUNK  128
#define NCHUNK   (K_TOT / K_CHUNK)  // 144

// ---------------- device scratch ----------------
__device__ __half g_a[O_TOT * K_TOT];             // A fp16, [o][l*2048+c]   9.4MB
__device__ __half g_b[(size_t)NPIX * K_TOT];      // B fp16, [p][l*2048+c]   151MB
__device__ float g_cwt[K_TOT * L_TOT];
__device__ float g_part[18 * L_TOT * NPIX];
__device__ float g_sigma[L_TOT * NPIX];
__device__ float g_smax[L_TOT * NPIX];
__device__ float g_scale[L_TOT];
__device__ float g_shift[L_TOT];

// ---------------- helpers ----------------
__device__ __forceinline__ uint32_t smem_u32(const void* p) {
    uint32_t a;
    asm("{ .reg .u64 t; cvta.to.shared.u64 t, %1; cvt.u32.u64 %0, t; }" : "=r"(a) : "l"(p));
    return a;
}
__device__ __forceinline__ void ldsm4(uint32_t* r, uint32_t addr) {
    asm volatile("ldmatrix.sync.aligned.m8n8.x4.shared.b16 {%0,%1,%2,%3}, [%4];"
        : "=r"(r[0]), "=r"(r[1]), "=r"(r[2]), "=r"(r[3]) : "r"(addr));
}
__device__ __forceinline__ void mma16816(float* d, const uint32_t* a, const uint32_t* b) {
    asm volatile(
        "mma.sync.aligned.m16n8k16.row.col.f32.f16.f16.f32 "
        "{%0,%1,%2,%3}, {%4,%5,%6,%7}, {%8,%9}, {%0,%1,%2,%3};"
        : "+f"(d[0]), "+f"(d[1]), "+f"(d[2]), "+f"(d[3])
        : "r"(a[0]), "r"(a[1]), "r"(a[2]), "r"(a[3]), "r"(b[0]), "r"(b[1]));
}
#define CP_ASYNC16(dst, src) \
    asm volatile("cp.async.cg.shared.global [%0], [%1], 16;" \
        :: "r"((uint32_t)(dst)), "l"(src) : "memory")
#define CP_COMMIT()  asm volatile("cp.async.commit_group;" ::: "memory")
#define CP_WAIT0()   asm volatile("cp.async.wait_group 0;" ::: "memory")
__device__ __forceinline__ unsigned long long ffma2(unsigned long long a,
                                                    unsigned long long b,
                                                    unsigned long long c) {
    unsigned long long d;
    asm("fma.rn.f32x2 %0, %1, %2, %3;" : "=l"(d) : "l"(a), "l"(b), "l"(c));
    return d;
}
__device__ __forceinline__ unsigned long long pack2(float lo, float hi) {
    unsigned long long d;
    asm("mov.b64 %0, {%1, %2};" : "=l"(d) : "f"(lo), "f"(hi));
    return d;
}
union U2F { unsigned long long u; float2 f; };

// ---------------- GEMM SMEM layout ----------------
#define ROW_B     272u                      // 128 fp16 = 256B + 16B pad
#define A_TILE_B  (128u * ROW_B)            // 34816
#define B_TILE_B  (64u * ROW_B)             // 17408
#define BUF_B     (A_TILE_B + B_TILE_B)     // 52224
#define SMEM_GEMM (2u * BUF_B)              // 104448

// ================= A prep: weight fp32 -> fp16, [o][l*2048+c] =================
__global__ __launch_bounds__(256) void prep_a(const float* __restrict__ w) {
    int t = blockIdx.x * 256 + threadIdx.x;     // O_TOT*C_TOT
    int o = t >> 11, c = t & 2047;
    const float* src = w + (size_t)o * K_TOT + c * 9;
#pragma unroll
    for (int l = 0; l < 9; l++)
        g_a[(size_t)o * K_TOT + l * C_TOT + c] = __float2half_rn(src[l]);
}

// ================= conv path =================
__global__ __launch_bounds__(256) void transpose_cw(const float* __restrict__ cw) {
    int i = blockIdx.x * 256 + threadIdx.x;
    if (i < K_TOT * L_TOT) {
        int R = i / 9, j = i - R * 9;
        int l = R >> 11, c = R & 2047;
        g_cwt[i] = cw[(size_t)j * K_TOT + c * 9 + l];
    }
}

__global__ __launch_bounds__(256) void conv_partial(const float* __restrict__ x) {
    extern __shared__ char cvsm[];
    unsigned long long* cw2 = (unsigned long long*)cvsm;   // [1024*9]
    const int tid = threadIdx.x;
    const int p0  = blockIdx.x * 512;
    const int l   = blockIdx.y >> 1;
    const int c0  = (blockIdx.y & 1) << 10;
    const int dy  = l / 3 - 1, dx = l % 3 - 1;

    const float* src = g_cwt + (size_t)(l * C_TOT + c0) * 9;
    for (int i = tid; i < 1024 * 9; i += 256) {
        float v = src[i];
        cw2[i] = pack2(v, v);
    }

    int pA = p0 + tid, pB = pA + 256;
    int nA = pA >> 10, remA = pA & 1023, yA = remA >> 5, xA = remA & 31;
    int nB = pB >> 10, remB = pB & 1023, yB = remB >> 5, xB = remB & 31;
    int yyA = yA + dy, xxA = xA + dx;
    int yyB = yB + dy, xxB = xB + dx;
    bool vA = ((unsigned)yyA < 32u) && ((unsigned)xxA < 32u);
    bool vB = ((unsigned)yyB < 32u) && ((unsigned)xxB < 32u);
    const float* ptrA = x + ((size_t)nA << 21) + (yyA << 5) + xxA;
    const float* ptrB = x + ((size_t)nB << 21) + (yyB << 5) + xxB;
    __syncthreads();

    unsigned long long acc[9];
#pragma unroll
    for (int j = 0; j < 9; j++) acc[j] = 0ULL;

#pragma unroll 4
    for (int ct = 0; ct < 1024; ct++) {
        int c = c0 + ct;
        float fA = vA ? ptrA[(size_t)c << 10] : 0.f;
        float fB = vB ? ptrB[(size_t)c << 10] : 0.f;
        unsigned long long pk = pack2(fA, fB);
#pragma unroll
        for (int j = 0; j < 9; j++)
            acc[j] = ffma2(pk, cw2[ct * 9 + j], acc[j]);
    }
    const size_t base = (size_t)blockIdx.y * (L_TOT * NPIX);
#pragma unroll
    for (int j = 0; j < 9; j++) {
        U2F u; u.u = acc[j];
        g_part[base + (size_t)j * NPIX + pA] = u.f.x;
        g_part[base + (size_t)j * NPIX + pB] = u.f.y;
    }
}

__global__ __launch_bounds__(256) void conv_reduce() {
    int i = blockIdx.x * 256 + threadIdx.x;
    if (i < L_TOT * NPIX) {
        float s = 0.f;
#pragma unroll
        for (int ch = 0; ch < 18; ch++) s += g_part[(size_t)ch * (L_TOT * NPIX) + i];
        g_sigma[i] = s;
    }
}

__global__ __launch_bounds__(256) void bn_stats(const float* __restrict__ gamma,
                                                const float* __restrict__ beta) {
    __shared__ float shs[256], shq[256];
    const int j = blockIdx.x, tid = threadIdx.x;
    float s = 0.f, q = 0.f;
    for (int i = tid; i < NPIX; i += 256) {
        float v = g_sigma[j * NPIX + i];
        s += v; q += v * v;
    }
    shs[tid] = s; shq[tid] = q;
    __syncthreads();
    for (int st = 128; st > 0; st >>= 1) {
        if (tid < st) { shs[tid] += shs[tid + st]; shq[tid] += shq[tid + st]; }
        __syncthreads();
    }
    if (tid == 0) {
        float mean = shs[0] * (1.f / NPIX);
        float var  = shq[0] * (1.f / NPIX) - mean * mean;
        float inv  = rsqrtf(var + 1e-5f);
        float sc   = gamma[j] * inv;
        g_scale[j] = sc;
        g_shift[j] = beta[j] - mean * sc;
    }
}

__global__ __launch_bounds__(256) void softmax_k() {
    int p = blockIdx.x * 256 + threadIdx.x;
    float v[9];
    float m = -1e30f;
#pragma unroll
    for (int j = 0; j < 9; j++) {
        v[j] = g_sigma[j * NPIX + p] * g_scale[j] + g_shift[j];
        m = fmaxf(m, v[j]);
    }
    float s = 0.f;
#pragma unroll
    for (int j = 0; j < 9; j++) { v[j] = expf(v[j] - m); s += v[j]; }
    float inv = 1.f / s;
#pragma unroll
    for (int j = 0; j < 9; j++) g_smax[j * NPIX + p] = v[j] * inv;
}

// ================= B producer: g_b[p][l*2048+c] = fp16(x_shift_l[c,p] * s_l[p]) =================
// grid (NPIX/64, C_TOT/64, 9), 256 threads. Read coalesced over p, smem transpose,
// write coalesced over c.
__global__ __launch_bounds__(256) void produce_b(const float* __restrict__ x) {
    __shared__ float t[64][68];
    __shared__ float s_sh[64];
    const int tid = threadIdx.x;
    const int p0 = blockIdx.x * 64;
    const int c0 = blockIdx.y * 64;
    const int l  = blockIdx.z;
    const int dy = l / 3 - 1, dx = l % 3 - 1;

    if (tid < 64) s_sh[tid] = g_smax[l * NPIX + p0 + tid];
    __syncthreads();

    const int pc = tid & 63;
    const int cr = tid >> 6;          // 0..3
    int p = p0 + pc;
    int n = p >> 10, rem = p & 1023, y = rem >> 5, xx = rem & 31;
    int yy = y + dy, xc = xx + dx;
    bool valid = ((unsigned)yy < 32u) && ((unsigned)xc < 32u);
    const float* xp = x + ((size_t)n << 21) + (yy << 5) + xc;
    float sf = s_sh[pc];

#pragma unroll
    for (int it = 0; it < 16; it++) {
        int c = cr + it * 4;
        t[c][pc] = valid ? xp[(size_t)(c0 + c) << 10] * sf : 0.f;
    }
    __syncthreads();

    const size_t colbase = (size_t)l * C_TOT + c0 + pc;
#pragma unroll
    for (int it = 0; it < 16; it++) {
        int prow = cr + it * 4;
        g_b[(size_t)(p0 + prow) * K_TOT + colbase] = __float2half_rn(t[pc][prow]);
    }
}

// ================= main GEMM: pure fp16 mma.sync, dual cp.async =================
// grid (64, 2); 256 threads = 8 warps (4 m x 2 n); warp tile 32x32; K_CHUNK=128
__global__ __launch_bounds__(256, 1) void gemm_mma(float* __restrict__ out) {
    extern __shared__ char smem_raw[];
    const uint32_t base = smem_u32(smem_raw);

    const int tid  = threadIdx.x;
    const int lane = tid & 31;
    const int wid  = tid >> 5;
    const int warp_m = wid & 3;
    const int warp_n = wid >> 2;
    const int p0     = blockIdx.x * N_TILE;
    const int o_base = blockIdx.y * M_TILE;
    const int n_img  = p0 >> 10;

    // cp.async geometry
    const int aRowT = tid >> 4;               // 0..15, +16*it
    const int aC16  = tid & 15;
    const __half* ag = g_a + (size_t)(o_base + aRowT) * K_TOT + aC16 * 8;
    const int bRowT = tid >> 2;               // 0..63
    const int bC16  = tid & 3;                // +4*it
    const __half* bg = g_b + (size_t)(p0 + bRowT) * K_TOT + bC16 * 8;

    const uint32_t aRow  = (uint32_t)(warp_m * 32 + (lane & 15));
    const uint32_t aColB = (uint32_t)(((lane >> 4) & 1) * 16);
    const uint32_t bRow  = (uint32_t)(warp_n * 32 + ((lane >> 4) & 1) * 8 + (lane & 7));
    const uint32_t bColB = (uint32_t)(((lane >> 3) & 1) * 16);

    float acc[2][4][4];
#pragma unroll
    for (int a = 0; a < 2; a++)
#pragma unroll
        for (int b = 0; b < 4; b++)
#pragma unroll
            for (int c = 0; c < 4; c++) acc[a][b][c] = 0.f;

    auto CPA = [&](int kt, int buf) {
        uint32_t aB = base + (uint32_t)buf * BUF_B
                    + (uint32_t)aRowT * ROW_B + (uint32_t)aC16 * 16;
        const __half* ga = ag + (size_t)kt * K_CHUNK;
#pragma unroll
        for (int it = 0; it < 8; it++)
            CP_ASYNC16(aB + (uint32_t)it * 16u * ROW_B, ga + (size_t)it * 16 * K_TOT);
        uint32_t bB = base + (uint32_t)buf * BUF_B + A_TILE_B
                    + (uint32_t)bRowT * ROW_B + (uint32_t)bC16 * 16;
        const __half* gb = bg + (size_t)kt * K_CHUNK;
#pragma unroll
        for (int it = 0; it < 4; it++)
            CP_ASYNC16(bB + (uint32_t)it * 64u, gb + (size_t)it * 32);
        CP_COMMIT();
    };

    auto COMPUTE = [&](int buf) {
        uint32_t aB = base + (uint32_t)buf * BUF_B;
        uint32_t bB = aB + A_TILE_B;
#pragma unroll
        for (int ks = 0; ks < 8; ks++) {
            uint32_t aF[2][4], bF[2][4];
#pragma unroll
            for (int ms = 0; ms < 2; ms++)
                ldsm4(aF[ms], aB + (aRow + ms * 16) * ROW_B + aColB + ks * 32);
#pragma unroll
            for (int np = 0; np < 2; np++)
                ldsm4(bF[np], bB + (bRow + np * 16) * ROW_B + bColB + ks * 32);
#pragma unroll
            for (int ms = 0; ms < 2; ms++)
#pragma unroll
                for (int ns = 0; ns < 4; ns++)
                    mma16816(acc[ms][ns], aF[ms], &bF[ns >> 1][(ns & 1) * 2]);
        }
    };

    CPA(0, 0);
    CP_WAIT0();
    __syncthreads();

    for (int kt = 0; kt < NCHUNK; kt++) {
        const int buf = kt & 1;
        if (kt + 1 < NCHUNK) CPA(kt + 1, buf ^ 1);
        COMPUTE(buf);
        CP_WAIT0();
        __syncthreads();
    }

    const int hw0 = (p0 & 1023);
#pragma unroll
    for (int ms = 0; ms < 2; ms++)
#pragma unroll
        for (int ns = 0; ns < 4; ns++) {
            int row  = o_base + warp_m * 32 + ms * 16 + (lane >> 2);
            int coln = hw0 + warp_n * 32 + ns * 8 + (lane & 3) * 2;
            float* p1 = out + (((size_t)(n_img * O_TOT + row)) << 10) + coln;
            *(float2*)p1 = make_float2(acc[ms][ns][0], acc[ms][ns][1]);
            float* p2 = p1 + ((size_t)8 << 10);
            *(float2*)p2 = make_float2(acc[ms][ns][2], acc[ms][ns][3]);
        }
}

// ---------------- launch ----------------
extern "C" void kernel_launch(void* const* d_in, const int* in_sizes, int n_in,
                              void* d_out, int out_size) {
    const float* x      = (const float*)d_in[0];
    const float* conv_w = (const float*)d_in[1];
    const float* gamma  = (const float*)d_in[2];
    const float* beta   = (const float*)d_in[3];
    const float* weight = (const float*)d_in[4];
    float* out = (float*)d_out;

    cudaFuncSetAttribute(gemm_mma, cudaFuncAttributeMaxDynamicSharedMemorySize, SMEM_GEMM);
    cudaFuncSetAttribute(conv_partial, cudaFuncAttributeMaxDynamicSharedMemorySize, 1024 * 9 * 8);

    prep_a      <<<(O_TOT * C_TOT) / 256, 256>>>(weight);
    transpose_cw<<<(K_TOT * L_TOT + 255) / 256, 256>>>(conv_w);
    conv_partial<<<dim3(8, 18), 256, 1024 * 9 * 8>>>(x);
    conv_reduce <<<(L_TOT * NPIX + 255) / 256, 256>>>();
    bn_stats    <<<9, 256>>>(gamma, beta);
    softmax_k   <<<NPIX / 256, 256>>>();
    produce_b   <<<dim3(NPIX / 64, C_TOT / 64, 9), 256>>>(x);
    gemm_mma    <<<dim3(NPIX / N_TILE, O_TOT / M_TILE), 256, SMEM_GEMM>>>(out);
}

// round 7
// speedup vs baseline: 1.3924x; 1.3924x over previous
#include <cuda_runtime.h>
#include <cuda_fp16.h>
#include <cstdint>

// ---------------- problem constants ----------------
#define C_TOT   2048
#define L_TOT   9
#define K_TOT   (C_TOT * L_TOT)     // 18432
#define NPIX    4096
#define O_TOT   256

// ---------------- GEMM tiling ----------------
#define N_TILE   64
#define M_TILE   128
#define K_CHUNK  128
#define NCHUNK   (K_TOT / K_CHUNK)  // 144 = 9 l * 16

// ---------------- device scratch ----------------
__device__ __half g_a[O_TOT * K_TOT];           // A fp16, [o][l*2048+c]  9.4MB
__device__ __half g_xt[NPIX * C_TOT];           // fp16 x-transpose [p][c] 16.8MB
__device__ float g_cwt[K_TOT * L_TOT];
__device__ float g_part[18 * L_TOT * NPIX];
__device__ float g_sigma[L_TOT * NPIX];
__device__ float g_smax[L_TOT * NPIX];
__device__ float g_scale[L_TOT];
__device__ float g_shift[L_TOT];

// ---------------- helpers ----------------
__device__ __forceinline__ uint32_t smem_u32(const void* p) {
    uint32_t a;
    asm("{ .reg .u64 t; cvta.to.shared.u64 t, %1; cvt.u32.u64 %0, t; }" : "=r"(a) : "l"(p));
    return a;
}
__device__ __forceinline__ void ldsm4(uint32_t* r, uint32_t addr) {
    asm volatile("ldmatrix.sync.aligned.m8n8.x4.shared.b16 {%0,%1,%2,%3}, [%4];"
        : "=r"(r[0]), "=r"(r[1]), "=r"(r[2]), "=r"(r[3]) : "r"(addr));
}
__device__ __forceinline__ void mma16816(float* d, const uint32_t* a, const uint32_t* b) {
    asm volatile(
        "mma.sync.aligned.m16n8k16.row.col.f32.f16.f16.f32 "
        "{%0,%1,%2,%3}, {%4,%5,%6,%7}, {%8,%9}, {%0,%1,%2,%3};"
        : "+f"(d[0]), "+f"(d[1]), "+f"(d[2]), "+f"(d[3])
        : "r"(a[0]), "r"(a[1]), "r"(a[2]), "r"(a[3]), "r"(b[0]), "r"(b[1]));
}
#define CP_ASYNC16(dst, src) \
    asm volatile("cp.async.cg.shared.global [%0], [%1], 16;" \
        :: "r"((uint32_t)(dst)), "l"(src) : "memory")
#define CP_ASYNC16Z(dst, src, ssz) \
    asm volatile("cp.async.cg.shared.global [%0], [%1], 16, %2;" \
        :: "r"((uint32_t)(dst)), "l"(src), "r"(ssz) : "memory")
#define CP_COMMIT()  asm volatile("cp.async.commit_group;" ::: "memory")
#define CP_WAIT0()   asm volatile("cp.async.wait_group 0;" ::: "memory")
__device__ __forceinline__ unsigned long long ffma2(unsigned long long a,
                                                    unsigned long long b,
                                                    unsigned long long c) {
    unsigned long long d;
    asm("fma.rn.f32x2 %0, %1, %2, %3;" : "=l"(d) : "l"(a), "l"(b), "l"(c));
    return d;
}
__device__ __forceinline__ unsigned long long pack2(float lo, float hi) {
    unsigned long long d;
    asm("mov.b64 %0, {%1, %2};" : "=l"(d) : "f"(lo), "f"(hi));
    return d;
}
union U2F { unsigned long long u; float2 f; };

// ---------------- GEMM SMEM layout ----------------
#define ROW_B     272u                      // 128 fp16 = 256B + 16B pad
#define A_TILE_B  (128u * ROW_B)            // 34816
#define B_TILE_B  (64u * ROW_B)             // 17408
#define BUF_B     (A_TILE_B + B_TILE_B)     // 52224
#define OFF_S     (2u * BUF_B)
#define SMEM_GEMM (OFF_S + 9u * 64u * 4u)   // 106752

// ================= A prep =================
__global__ __launch_bounds__(256) void prep_a(const float* __restrict__ w) {
    int t = blockIdx.x * 256 + threadIdx.x;     // O_TOT*C_TOT
    int o = t >> 11, c = t & 2047;
    const float* src = w + (size_t)o * K_TOT + c * 9;
#pragma unroll
    for (int l = 0; l < 9; l++)
        g_a[(size_t)o * K_TOT + l * C_TOT + c] = __float2half_rn(src[l]);
}

// ================= x transpose: g_xt[p][c] = fp16(x[n,c,y,x]) =================
__global__ __launch_bounds__(256) void transpose_x(const float* __restrict__ x) {
    __shared__ float t[64][65];
    const int tid = threadIdx.x;
    const int p0 = blockIdx.x * 64;
    const int c0 = blockIdx.y * 64;
    const int pc = tid & 63;
    const int cr = tid >> 6;            // 0..3
    const int p = p0 + pc;
    const int n = p >> 10, hw = p & 1023;
    const float* xp = x + (((size_t)(n * C_TOT + c0)) << 10) + hw;
#pragma unroll
    for (int it = 0; it < 16; it++) {
        int c = cr + it * 4;
        t[c][pc] = xp[(size_t)c << 10];
    }
    __syncthreads();
#pragma unroll
    for (int it = 0; it < 16; it++) {
        int prow = cr + it * 4;
        g_xt[(size_t)(p0 + prow) * C_TOT + c0 + pc] = __float2half_rn(t[pc][prow]);
    }
}

// ================= conv path =================
__global__ __launch_bounds__(256) void transpose_cw(const float* __restrict__ cw) {
    int i = blockIdx.x * 256 + threadIdx.x;
    if (i < K_TOT * L_TOT) {
        int R = i / 9, j = i - R * 9;
        int l = R >> 11, c = R & 2047;
        g_cwt[i] = cw[(size_t)j * K_TOT + c * 9 + l];
    }
}

__global__ __launch_bounds__(256) void conv_partial(const float* __restrict__ x) {
    extern __shared__ char cvsm[];
    unsigned long long* cw2 = (unsigned long long*)cvsm;   // [1024*9]
    const int tid = threadIdx.x;
    const int p0  = blockIdx.x * 512;
    const int l   = blockIdx.y >> 1;
    const int c0  = (blockIdx.y & 1) << 10;
    const int dy  = l / 3 - 1, dx = l % 3 - 1;

    const float* src = g_cwt + (size_t)(l * C_TOT + c0) * 9;
    for (int i = tid; i < 1024 * 9; i += 256) {
        float v = src[i];
        cw2[i] = pack2(v, v);
    }

    int pA = p0 + tid, pB = pA + 256;
    int nA = pA >> 10, remA = pA & 1023, yA = remA >> 5, xA = remA & 31;
    int nB = pB >> 10, remB = pB & 1023, yB = remB >> 5, xB = remB & 31;
    int yyA = yA + dy, xxA = xA + dx;
    int yyB = yB + dy, xxB = xB + dx;
    bool vA = ((unsigned)yyA < 32u) && ((unsigned)xxA < 32u);
    bool vB = ((unsigned)yyB < 32u) && ((unsigned)xxB < 32u);
    const float* ptrA = x + ((size_t)nA << 21) + (yyA << 5) + xxA;
    const float* ptrB = x + ((size_t)nB << 21) + (yyB << 5) + xxB;
    __syncthreads();

    unsigned long long acc[9];
#pragma unroll
    for (int j = 0; j < 9; j++) acc[j] = 0ULL;

#pragma unroll 4
    for (int ct = 0; ct < 1024; ct++) {
        int c = c0 + ct;
        float fA = vA ? ptrA[(size_t)c << 10] : 0.f;
        float fB = vB ? ptrB[(size_t)c << 10] : 0.f;
        unsigned long long pk = pack2(fA, fB);
#pragma unroll
        for (int j = 0; j < 9; j++)
            acc[j] = ffma2(pk, cw2[ct * 9 + j], acc[j]);
    }
    const size_t base = (size_t)blockIdx.y * (L_TOT * NPIX);
#pragma unroll
    for (int j = 0; j < 9; j++) {
        U2F u; u.u = acc[j];
        g_part[base + (size_t)j * NPIX + pA] = u.f.x;
        g_part[base + (size_t)j * NPIX + pB] = u.f.y;
    }
}

__global__ __launch_bounds__(256) void conv_reduce() {
    int i = blockIdx.x * 256 + threadIdx.x;
    if (i < L_TOT * NPIX) {
        float s = 0.f;
#pragma unroll
        for (int ch = 0; ch < 18; ch++) s += g_part[(size_t)ch * (L_TOT * NPIX) + i];
        g_sigma[i] = s;
    }
}

__global__ __launch_bounds__(256) void bn_stats(const float* __restrict__ gamma,
                                                const float* __restrict__ beta) {
    __shared__ float shs[256], shq[256];
    const int j = blockIdx.x, tid = threadIdx.x;
    float s = 0.f, q = 0.f;
    for (int i = tid; i < NPIX; i += 256) {
        float v = g_sigma[j * NPIX + i];
        s += v; q += v * v;
    }
    shs[tid] = s; shq[tid] = q;
    __syncthreads();
    for (int st = 128; st > 0; st >>= 1) {
        if (tid < st) { shs[tid] += shs[tid + st]; shq[tid] += shq[tid + st]; }
        __syncthreads();
    }
    if (tid == 0) {
        float mean = shs[0] * (1.f / NPIX);
        float var  = shq[0] * (1.f / NPIX) - mean * mean;
        float inv  = rsqrtf(var + 1e-5f);
        float sc   = gamma[j] * inv;
        g_scale[j] = sc;
        g_shift[j] = beta[j] - mean * sc;
    }
}

__global__ __launch_bounds__(256) void softmax_k() {
    int p = blockIdx.x * 256 + threadIdx.x;
    float v[9];
    float m = -1e30f;
#pragma unroll
    for (int j = 0; j < 9; j++) {
        v[j] = g_sigma[j * NPIX + p] * g_scale[j] + g_shift[j];
        m = fmaxf(m, v[j]);
    }
    float s = 0.f;
#pragma unroll
    for (int j = 0; j < 9; j++) { v[j] = expf(v[j] - m); s += v[j]; }
    float inv = 1.f / s;
#pragma unroll
    for (int j = 0; j < 9; j++) g_smax[j * NPIX + p] = v[j] * inv;
}

// ================= main GEMM =================
// out[o,p] = sum_l s_l[p] * sum_c A[o][l*2048+c] * xt[p + off_l][c]
// grid (64, 2); 256 threads = 8 warps (4 m x 2 n); warp tile 32x32; K_CHUNK=128
__global__ __launch_bounds__(256, 1) void gemm_mma(float* __restrict__ out) {
    extern __shared__ char smem_raw[];
    const uint32_t base = smem_u32(smem_raw);
    float* s_sh = (float*)(smem_raw + OFF_S);

    const int tid  = threadIdx.x;
    const int lane = tid & 31;
    const int wid  = tid >> 5;
    const int warp_m = wid & 3;
    const int warp_n = wid >> 2;
    const int p0     = blockIdx.x * N_TILE;
    const int o_base = blockIdx.y * M_TILE;
    const int n_img  = p0 >> 10;

    for (int i = tid; i < 9 * N_TILE; i += 256) {
        int l = i >> 6, pp = i & 63;
        s_sh[i] = g_smax[l * NPIX + p0 + pp];
    }
    __syncthreads();

    // cp.async geometry
    const int aRowT = tid >> 4;               // 0..15, +16*it
    const int aC16  = tid & 15;
    const __half* ag = g_a + (size_t)(o_base + aRowT) * K_TOT + aC16 * 8;
    const int bRowT = tid >> 2;               // 0..63 (pixel within tile)
    const int bC16  = tid & 3;
    const int pb = p0 + bRowT;
    const int yb = (pb & 1023) >> 5, xb = pb & 31;
    const __half* xt_row = g_xt + (size_t)pb * C_TOT + bC16 * 8;

    const uint32_t aRow  = (uint32_t)(warp_m * 32 + (lane & 15));
    const uint32_t aColB = (uint32_t)(((lane >> 4) & 1) * 16);
    const uint32_t bRow  = (uint32_t)(warp_n * 32 + ((lane >> 4) & 1) * 8 + (lane & 7));
    const uint32_t bColB = (uint32_t)(((lane >> 3) & 1) * 16);

    float fin[2][4][4], cur[2][4][4];
#pragma unroll
    for (int a = 0; a < 2; a++)
#pragma unroll
        for (int b = 0; b < 4; b++)
#pragma unroll
            for (int c = 0; c < 4; c++) { fin[a][b][c] = 0.f; cur[a][b][c] = 0.f; }

    auto CPA = [&](int kt, int buf) {
        uint32_t aB = base + (uint32_t)buf * BUF_B
                    + (uint32_t)aRowT * ROW_B + (uint32_t)aC16 * 16;
        const __half* ga = ag + (size_t)kt * K_CHUNK;
#pragma unroll
        for (int it = 0; it < 8; it++)
            CP_ASYNC16(aB + (uint32_t)it * 16u * ROW_B, ga + (size_t)it * 16 * K_TOT);
        // B: shifted row of g_xt, zero-filled when out of image
        int l  = kt >> 4;
        int dy = l / 3 - 1, dx = l - l / 3 * 3 - 1;
        bool v = ((unsigned)(yb + dy) < 32u) & ((unsigned)(xb + dx) < 32u);
        uint32_t ssz = v ? 16u : 0u;
        const __half* gb = v ? (xt_row + (ptrdiff_t)(dy * 32 + dx) * C_TOT) : g_xt;
        gb += (size_t)(kt & 15) * K_CHUNK;
        uint32_t bB = base + (uint32_t)buf * BUF_B + A_TILE_B
                    + (uint32_t)bRowT * ROW_B + (uint32_t)bC16 * 16;
#pragma unroll
        for (int it = 0; it < 4; it++)
            CP_ASYNC16Z(bB + (uint32_t)it * 64u, gb + (size_t)it * 32, ssz);
        CP_COMMIT();
    };

    auto COMPUTE = [&](int buf) {
        uint32_t aB = base + (uint32_t)buf * BUF_B;
        uint32_t bB = aB + A_TILE_B;
#pragma unroll
        for (int ks = 0; ks < 8; ks++) {
            uint32_t aF[2][4], bF[2][4];
#pragma unroll
            for (int ms = 0; ms < 2; ms++)
                ldsm4(aF[ms], aB + (aRow + ms * 16) * ROW_B + aColB + ks * 32);
#pragma unroll
            for (int np = 0; np < 2; np++)
                ldsm4(bF[np], bB + (bRow + np * 16) * ROW_B + bColB + ks * 32);
#pragma unroll
            for (int ms = 0; ms < 2; ms++)
#pragma unroll
                for (int ns = 0; ns < 4; ns++)
                    mma16816(cur[ms][ns], aF[ms], &bF[ns >> 1][(ns & 1) * 2]);
        }
    };

    CPA(0, 0);
    CP_WAIT0();
    __syncthreads();

    for (int lt = 0; lt < 9; lt++) {
#pragma unroll 1
        for (int ki = 0; ki < 16; ki++) {
            const int kt = lt * 16 + ki;
            const int buf = kt & 1;
            if (kt + 1 < NCHUNK) CPA(kt + 1, buf ^ 1);
            COMPUTE(buf);
            CP_WAIT0();
            __syncthreads();
        }
        // l-boundary: fold softmax scale into final accumulator
#pragma unroll
        for (int ns = 0; ns < 4; ns++) {
            int cn = warp_n * 32 + ns * 8 + (lane & 3) * 2;
            float s0 = s_sh[lt * 64 + cn];
            float s1 = s_sh[lt * 64 + cn + 1];
#pragma unroll
            for (int ms = 0; ms < 2; ms++) {
                fin[ms][ns][0] += cur[ms][ns][0] * s0;
                fin[ms][ns][1] += cur[ms][ns][1] * s1;
                fin[ms][ns][2] += cur[ms][ns][2] * s0;
                fin[ms][ns][3] += cur[ms][ns][3] * s1;
                cur[ms][ns][0] = 0.f; cur[ms][ns][1] = 0.f;
                cur[ms][ns][2] = 0.f; cur[ms][ns][3] = 0.f;
            }
        }
    }

    const int hw0 = (p0 & 1023);
#pragma unroll
    for (int ms = 0; ms < 2; ms++)
#pragma unroll
        for (int ns = 0; ns < 4; ns++) {
            int row  = o_base + warp_m * 32 + ms * 16 + (lane >> 2);
            int coln = hw0 + warp_n * 32 + ns * 8 + (lane & 3) * 2;
            float* p1 = out + (((size_t)(n_img * O_TOT + row)) << 10) + coln;
            *(float2*)p1 = make_float2(fin[ms][ns][0], fin[ms][ns][1]);
            float* p2 = p1 + ((size_t)8 << 10);
            *(float2*)p2 = make_float2(fin[ms][ns][2], fin[ms][ns][3]);
        }
}

// ---------------- launch ----------------
extern "C" void kernel_launch(void* const* d_in, const int* in_sizes, int n_in,
                              void* d_out, int out_size) {
    const float* x      = (const float*)d_in[0];
    const float* conv_w = (const float*)d_in[1];
    const float* gamma  = (const float*)d_in[2];
    const float* beta   = (const float*)d_in[3];
    const float* weight = (const float*)d_in[4];
    float* out = (float*)d_out;

    cudaFuncSetAttribute(gemm_mma, cudaFuncAttributeMaxDynamicSharedMemorySize, SMEM_GEMM);
    cudaFuncSetAttribute(conv_partial, cudaFuncAttributeMaxDynamicSharedMemorySize, 1024 * 9 * 8);

    prep_a      <<<(O_TOT * C_TOT) / 256, 256>>>(weight);
    transpose_x <<<dim3(NPIX / 64, C_TOT / 64), 256>>>(x);
    transpose_cw<<<(K_TOT * L_TOT + 255) / 256, 256>>>(conv_w);
    conv_partial<<<dim3(8, 18), 256, 1024 * 9 * 8>>>(x);
    conv_reduce <<<(L_TOT * NPIX + 255) / 256, 256>>>();
    bn_stats    <<<9, 256>>>(gamma, beta);
    softmax_k   <<<NPIX / 256, 256>>>();
    gemm_mma    <<<dim3(NPIX / N_TILE, O_TOT / M_TILE), 256, SMEM_GEMM>>>(out);
}

// round 8
// speedup vs baseline: 1.9598x; 1.4075x over previous
#include <cuda_runtime.h>
#include <cuda_fp16.h>
#include <cstdint>

// ---------------- problem constants ----------------
#define C_TOT   2048
#define L_TOT   9
#define K_TOT   (C_TOT * L_TOT)     // 18432
#define NPIX    4096
#define O_TOT   256

// ---------------- GEMM tiling ----------------
#define N_TILE   64
#define M_TILE   128
#define K_CHUNK  128
#define NCHUNK   (K_TOT / K_CHUNK)  // 144 = 9 l * 16

// ---------------- conv tiling ----------------
#define CV_CCH   512                // c per chunk
#define CV_NCH   (C_TOT / CV_CCH)   // 4
#define CV_CHUNKS (L_TOT * CV_NCH)  // 36

// ---------------- device scratch ----------------
__device__ __half g_a[O_TOT * K_TOT];           // A fp16, [o][l*2048+c]  9.4MB
__device__ __half g_xt[NPIX * C_TOT];           // fp16 x-transpose [p][c] 16.8MB
__device__ float g_cwt[K_TOT * L_TOT];
__device__ float g_part[CV_CHUNKS * L_TOT * NPIX];
__device__ float g_sigma[L_TOT * NPIX];
__device__ float g_smax[L_TOT * NPIX];
__device__ float g_scale[L_TOT];
__device__ float g_shift[L_TOT];

// ---------------- helpers ----------------
__device__ __forceinline__ uint32_t smem_u32(const void* p) {
    uint32_t a;
    asm("{ .reg .u64 t; cvta.to.shared.u64 t, %1; cvt.u32.u64 %0, t; }" : "=r"(a) : "l"(p));
    return a;
}
__device__ __forceinline__ void ldsm4(uint32_t* r, uint32_t addr) {
    asm volatile("ldmatrix.sync.aligned.m8n8.x4.shared.b16 {%0,%1,%2,%3}, [%4];"
        : "=r"(r[0]), "=r"(r[1]), "=r"(r[2]), "=r"(r[3]) : "r"(addr));
}
__device__ __forceinline__ void mma16816(float* d, const uint32_t* a, const uint32_t* b) {
    asm volatile(
        "mma.sync.aligned.m16n8k16.row.col.f32.f16.f16.f32 "
        "{%0,%1,%2,%3}, {%4,%5,%6,%7}, {%8,%9}, {%0,%1,%2,%3};"
        : "+f"(d[0]), "+f"(d[1]), "+f"(d[2]), "+f"(d[3])
        : "r"(a[0]), "r"(a[1]), "r"(a[2]), "r"(a[3]), "r"(b[0]), "r"(b[1]));
}
#define CP_ASYNC16(dst, src) \
    asm volatile("cp.async.cg.shared.global [%0], [%1], 16;" \
        :: "r"((uint32_t)(dst)), "l"(src) : "memory")
#define CP_ASYNC16Z(dst, src, ssz) \
    asm volatile("cp.async.cg.shared.global [%0], [%1], 16, %2;" \
        :: "r"((uint32_t)(dst)), "l"(src), "r"(ssz) : "memory")
#define CP_COMMIT()  asm volatile("cp.async.commit_group;" ::: "memory")
#define CP_WAIT0()   asm volatile("cp.async.wait_group 0;" ::: "memory")
__device__ __forceinline__ unsigned long long ffma2(unsigned long long a,
                                                    unsigned long long b,
                                                    unsigned long long c) {
    unsigned long long d;
    asm("fma.rn.f32x2 %0, %1, %2, %3;" : "=l"(d) : "l"(a), "l"(b), "l"(c));
    return d;
}
__device__ __forceinline__ unsigned long long pack2(float lo, float hi) {
    unsigned long long d;
    asm("mov.b64 %0, {%1, %2};" : "=l"(d) : "f"(lo), "f"(hi));
    return d;
}
union U2F { unsigned long long u; float2 f; };

// ---------------- GEMM SMEM layout ----------------
#define ROW_B     272u                      // 128 fp16 = 256B + 16B pad
#define A_TILE_B  (128u * ROW_B)            // 34816
#define B_TILE_B  (64u * ROW_B)             // 17408
#define BUF_B     (A_TILE_B + B_TILE_B)     // 52224
#define OFF_S     (2u * BUF_B)
#define SMEM_GEMM (OFF_S + 9u * 64u * 4u)   // 106752

// ================= A prep =================
__global__ __launch_bounds__(256) void prep_a(const float* __restrict__ w) {
    int t = blockIdx.x * 256 + threadIdx.x;     // O_TOT*C_TOT
    int o = t >> 11, c = t & 2047;
    const float* src = w + (size_t)o * K_TOT + c * 9;
#pragma unroll
    for (int l = 0; l < 9; l++)
        g_a[(size_t)o * K_TOT + l * C_TOT + c] = __float2half_rn(src[l]);
}

// ================= x transpose: g_xt[p][c] = fp16(x[n,c,y,x]) =================
__global__ __launch_bounds__(256) void transpose_x(const float* __restrict__ x) {
    __shared__ float t[64][65];
    const int tid = threadIdx.x;
    const int p0 = blockIdx.x * 64;
    const int c0 = blockIdx.y * 64;
    const int pc = tid & 63;
    const int cr = tid >> 6;            // 0..3
    const int p = p0 + pc;
    const int n = p >> 10, hw = p & 1023;
    const float* xp = x + (((size_t)(n * C_TOT + c0)) << 10) + hw;
#pragma unroll
    for (int it = 0; it < 16; it++) {
        int c = cr + it * 4;
        t[c][pc] = xp[(size_t)c << 10];
    }
    __syncthreads();
#pragma unroll
    for (int it = 0; it < 16; it++) {
        int prow = cr + it * 4;
        g_xt[(size_t)(p0 + prow) * C_TOT + c0 + pc] = __float2half_rn(t[pc][prow]);
    }
}

// ================= conv path =================
__global__ __launch_bounds__(256) void transpose_cw(const float* __restrict__ cw) {
    int i = blockIdx.x * 256 + threadIdx.x;
    if (i < K_TOT * L_TOT) {
        int R = i / 9, j = i - R * 9;
        int l = R >> 11, c = R & 2047;
        g_cwt[i] = cw[(size_t)j * K_TOT + c * 9 + l];
    }
}

// grid (8, 36): 512-px tiles x (l, c-quarter). 256 threads, 2 px/thread (f32x2).
// Batched x loads (MLP=32/thread), 36KB smem -> 2 CTAs/SM.
__global__ __launch_bounds__(256) void conv_partial(const float* __restrict__ x) {
    extern __shared__ char cvsm[];
    unsigned long long* cw2 = (unsigned long long*)cvsm;   // [CV_CCH*9] duplicated
    const int tid = threadIdx.x;
    const int p0  = blockIdx.x * 512;
    const int l   = blockIdx.y / CV_NCH;
    const int c0  = (blockIdx.y % CV_NCH) * CV_CCH;
    const int dy  = l / 3 - 1, dx = l % 3 - 1;

    const float* src = g_cwt + (size_t)(l * C_TOT + c0) * 9;
    for (int i = tid; i < CV_CCH * 9; i += 256) {
        float v = src[i];
        cw2[i] = pack2(v, v);
    }

    int pA = p0 + tid, pB = pA + 256;
    int nA = pA >> 10, remA = pA & 1023, yA = remA >> 5, xA = remA & 31;
    int nB = pB >> 10, remB = pB & 1023, yB = remB >> 5, xB = remB & 31;
    int yyA = yA + dy, xxA = xA + dx;
    int yyB = yB + dy, xxB = xB + dx;
    bool vA = ((unsigned)yyA < 32u) && ((unsigned)xxA < 32u);
    bool vB = ((unsigned)yyB < 32u) && ((unsigned)xxB < 32u);
    const float* ptrA = x + ((size_t)nA << 21) + ((size_t)c0 << 10) + (yyA << 5) + xxA;
    const float* ptrB = x + ((size_t)nB << 21) + ((size_t)c0 << 10) + (yyB << 5) + xxB;
    __syncthreads();

    unsigned long long acc[9];
#pragma unroll
    for (int j = 0; j < 9; j++) acc[j] = 0ULL;

    for (int cg = 0; cg < CV_CCH; cg += 16) {
        float va[16], vb[16];
#pragma unroll
        for (int t = 0; t < 16; t++) {
            size_t off = (size_t)(cg + t) << 10;
            va[t] = vA ? ptrA[off] : 0.f;
            vb[t] = vB ? ptrB[off] : 0.f;
        }
#pragma unroll
        for (int t = 0; t < 16; t++) {
            unsigned long long pk = pack2(va[t], vb[t]);
            const unsigned long long* wrow = cw2 + (cg + t) * 9;
#pragma unroll
            for (int j = 0; j < 9; j++)
                acc[j] = ffma2(pk, wrow[j], acc[j]);
        }
    }
    const size_t base = (size_t)blockIdx.y * (L_TOT * NPIX);
#pragma unroll
    for (int j = 0; j < 9; j++) {
        U2F u; u.u = acc[j];
        g_part[base + (size_t)j * NPIX + pA] = u.f.x;
        g_part[base + (size_t)j * NPIX + pB] = u.f.y;
    }
}

__global__ __launch_bounds__(256) void conv_reduce() {
    int i = blockIdx.x * 256 + threadIdx.x;
    if (i < L_TOT * NPIX) {
        float s = 0.f;
#pragma unroll
        for (int ch = 0; ch < CV_CHUNKS; ch++)
            s += g_part[(size_t)ch * (L_TOT * NPIX) + i];
        g_sigma[i] = s;
    }
}

__global__ __launch_bounds__(256) void bn_stats(const float* __restrict__ gamma,
                                                const float* __restrict__ beta) {
    __shared__ float shs[256], shq[256];
    const int j = blockIdx.x, tid = threadIdx.x;
    float s = 0.f, q = 0.f;
    for (int i = tid; i < NPIX; i += 256) {
        float v = g_sigma[j * NPIX + i];
        s += v; q += v * v;
    }
    shs[tid] = s; shq[tid] = q;
    __syncthreads();
    for (int st = 128; st > 0; st >>= 1) {
        if (tid < st) { shs[tid] += shs[tid + st]; shq[tid] += shq[tid + st]; }
        __syncthreads();
    }
    if (tid == 0) {
        float mean = shs[0] * (1.f / NPIX);
        float var  = shq[0] * (1.f / NPIX) - mean * mean;
        float inv  = rsqrtf(var + 1e-5f);
        float sc   = gamma[j] * inv;
        g_scale[j] = sc;
        g_shift[j] = beta[j] - mean * sc;
    }
}

__global__ __launch_bounds__(256) void softmax_k() {
    int p = blockIdx.x * 256 + threadIdx.x;
    float v[9];
    float m = -1e30f;
#pragma unroll
    for (int j = 0; j < 9; j++) {
        v[j] = g_sigma[j * NPIX + p] * g_scale[j] + g_shift[j];
        m = fmaxf(m, v[j]);
    }
    float s = 0.f;
#pragma unroll
    for (int j = 0; j < 9; j++) { v[j] = expf(v[j] - m); s += v[j]; }
    float inv = 1.f / s;
#pragma unroll
    for (int j = 0; j < 9; j++) g_smax[j * NPIX + p] = v[j] * inv;
}

// ================= main GEMM =================
// out[o,p] = sum_l s_l[p] * sum_c A[o][l*2048+c] * xt[p + off_l][c]
__global__ __launch_bounds__(256, 1) void gemm_mma(float* __restrict__ out) {
    extern __shared__ char smem_raw[];
    const uint32_t base = smem_u32(smem_raw);
    float* s_sh = (float*)(smem_raw + OFF_S);

    const int tid  = threadIdx.x;
    const int lane = tid & 31;
    const int wid  = tid >> 5;
    const int warp_m = wid & 3;
    const int warp_n = wid >> 2;
    const int p0     = blockIdx.x * N_TILE;
    const int o_base = blockIdx.y * M_TILE;
    const int n_img  = p0 >> 10;

    for (int i = tid; i < 9 * N_TILE; i += 256) {
        int l = i >> 6, pp = i & 63;
        s_sh[i] = g_smax[l * NPIX + p0 + pp];
    }
    __syncthreads();

    const int aRowT = tid >> 4;
    const int aC16  = tid & 15;
    const __half* ag = g_a + (size_t)(o_base + aRowT) * K_TOT + aC16 * 8;
    const int bRowT = tid >> 2;
    const int bC16  = tid & 3;
    const int pb = p0 + bRowT;
    const int yb = (pb & 1023) >> 5, xb = pb & 31;
    const __half* xt_row = g_xt + (size_t)pb * C_TOT + bC16 * 8;

    const uint32_t aRow  = (uint32_t)(warp_m * 32 + (lane & 15));
    const uint32_t aColB = (uint32_t)(((lane >> 4) & 1) * 16);
    const uint32_t bRow  = (uint32_t)(warp_n * 32 + ((lane >> 4) & 1) * 8 + (lane & 7));
    const uint32_t bColB = (uint32_t)(((lane >> 3) & 1) * 16);

    float fin[2][4][4], cur[2][4][4];
#pragma unroll
    for (int a = 0; a < 2; a++)
#pragma unroll
        for (int b = 0; b < 4; b++)
#pragma unroll
            for (int c = 0; c < 4; c++) { fin[a][b][c] = 0.f; cur[a][b][c] = 0.f; }

    auto CPA = [&](int kt, int buf) {
        uint32_t aB = base + (uint32_t)buf * BUF_B
                    + (uint32_t)aRowT * ROW_B + (uint32_t)aC16 * 16;
        const __half* ga = ag + (size_t)kt * K_CHUNK;
#pragma unroll
        for (int it = 0; it < 8; it++)
            CP_ASYNC16(aB + (uint32_t)it * 16u * ROW_B, ga + (size_t)it * 16 * K_TOT);
        int l  = kt >> 4;
        int dy = l / 3 - 1, dx = l - l / 3 * 3 - 1;
        bool v = ((unsigned)(yb + dy) < 32u) & ((unsigned)(xb + dx) < 32u);
        uint32_t ssz = v ? 16u : 0u;
        const __half* gb = v ? (xt_row + (ptrdiff_t)(dy * 32 + dx) * C_TOT) : g_xt;
        gb += (size_t)(kt & 15) * K_CHUNK;
        uint32_t bB = base + (uint32_t)buf * BUF_B + A_TILE_B
                    + (uint32_t)bRowT * ROW_B + (uint32_t)bC16 * 16;
#pragma unroll
        for (int it = 0; it < 4; it++)
            CP_ASYNC16Z(bB + (uint32_t)it * 64u, gb + (size_t)it * 32, ssz);
        CP_COMMIT();
    };

    auto COMPUTE = [&](int buf) {
        uint32_t aB = base + (uint32_t)buf * BUF_B;
        uint32_t bB = aB + A_TILE_B;
#pragma unroll
        for (int ks = 0; ks < 8; ks++) {
            uint32_t aF[2][4], bF[2][4];
#pragma unroll
            for (int ms = 0; ms < 2; ms++)
                ldsm4(aF[ms], aB + (aRow + ms * 16) * ROW_B + aColB + ks * 32);
#pragma unroll
            for (int np = 0; np < 2; np++)
                ldsm4(bF[np], bB + (bRow + np * 16) * ROW_B + bColB + ks * 32);
#pragma unroll
            for (int ms = 0; ms < 2; ms++)
#pragma unroll
                for (int ns = 0; ns < 4; ns++)
                    mma16816(cur[ms][ns], aF[ms], &bF[ns >> 1][(ns & 1) * 2]);
        }
    };

    CPA(0, 0);
    CP_WAIT0();
    __syncthreads();

    for (int lt = 0; lt < 9; lt++) {
#pragma unroll 1
        for (int ki = 0; ki < 16; ki++) {
            const int kt = lt * 16 + ki;
            const int buf = kt & 1;
            if (kt + 1 < NCHUNK) CPA(kt + 1, buf ^ 1);
            COMPUTE(buf);
            CP_WAIT0();
            __syncthreads();
        }
#pragma unroll
        for (int ns = 0; ns < 4; ns++) {
            int cn = warp_n * 32 + ns * 8 + (lane & 3) * 2;
            float s0 = s_sh[lt * 64 + cn];
            float s1 = s_sh[lt * 64 + cn + 1];
#pragma unroll
            for (int ms = 0; ms < 2; ms++) {
                fin[ms][ns][0] += cur[ms][ns][0] * s0;
                fin[ms][ns][1] += cur[ms][ns][1] * s1;
                fin[ms][ns][2] += cur[ms][ns][2] * s0;
                fin[ms][ns][3] += cur[ms][ns][3] * s1;
                cur[ms][ns][0] = 0.f; cur[ms][ns][1] = 0.f;
                cur[ms][ns][2] = 0.f; cur[ms][ns][3] = 0.f;
            }
        }
    }

    const int hw0 = (p0 & 1023);
#pragma unroll
    for (int ms = 0; ms < 2; ms++)
#pragma unroll
        for (int ns = 0; ns < 4; ns++) {
            int row  = o_base + warp_m * 32 + ms * 16 + (lane >> 2);
            int coln = hw0 + warp_n * 32 + ns * 8 + (lane & 3) * 2;
            float* p1 = out + (((size_t)(n_img * O_TOT + row)) << 10) + coln;
            *(float2*)p1 = make_float2(fin[ms][ns][0], fin[ms][ns][1]);
            float* p2 = p1 + ((size_t)8 << 10);
            *(float2*)p2 = make_float2(fin[ms][ns][2], fin[ms][ns][3]);
        }
}

// ---------------- launch ----------------
extern "C" void kernel_launch(void* const* d_in, const int* in_sizes, int n_in,
                              void* d_out, int out_size) {
    const float* x      = (const float*)d_in[0];
    const float* conv_w = (const float*)d_in[1];
    const float* gamma  = (const float*)d_in[2];
    const float* beta   = (const float*)d_in[3];
    const float* weight = (const float*)d_in[4];
    float* out = (float*)d_out;

    cudaFuncSetAttribute(gemm_mma, cudaFuncAttributeMaxDynamicSharedMemorySize, SMEM_GEMM);
    cudaFuncSetAttribute(conv_partial, cudaFuncAttributeMaxDynamicSharedMemorySize, CV_CCH * 9 * 8);

    prep_a      <<<(O_TOT * C_TOT) / 256, 256>>>(weight);
    transpose_x <<<dim3(NPIX / 64, C_TOT / 64), 256>>>(x);
    transpose_cw<<<(K_TOT * L_TOT + 255) / 256, 256>>>(conv_w);
    conv_partial<<<dim3(8, CV_CHUNKS), 256, CV_CCH * 9 * 8>>>(x);
    conv_reduce <<<(L_TOT * NPIX + 255) / 256, 256>>>();
    bn_stats    <<<9, 256>>>(gamma, beta);
    softmax_k   <<<NPIX / 256, 256>>>();
    gemm_mma    <<<dim3(NPIX / N_TILE, O_TOT / M_TILE), 256, SMEM_GEMM>>>(out);
}

// round 9
// speedup vs baseline: 2.0723x; 1.0574x over previous
#include <cuda_runtime.h>
#include <cuda_fp16.h>
#include <cstdint>

// ---------------- problem constants ----------------
#define C_TOT   2048
#define L_TOT   9
#define K_TOT   (C_TOT * L_TOT)     // 18432
#define NPIX    4096
#define O_TOT   256

// ---------------- GEMM tiling ----------------
#define N_TILE   64
#define M_TILE   128
#define K_CHUNK  128
#define NCHUNK   (K_TOT / K_CHUNK)  // 144 = 9 l * 16

// ---------------- conv tiling ----------------
#define CV_CCH   256                // c per chunk
#define CV_NCH   (C_TOT / CV_CCH)   // 8
#define CV_CHUNKS (L_TOT * CV_NCH)  // 72

// ---------------- device scratch ----------------
__device__ __half g_a[O_TOT * K_TOT];           // A fp16, [o][l*2048+c]  9.4MB
__device__ __half g_xt[NPIX * C_TOT];           // fp16 x-transpose [p][c] 16.8MB
__device__ float g_cwt[K_TOT * L_TOT];
__device__ float g_part[CV_CHUNKS * L_TOT * NPIX];
__device__ float g_sigma[L_TOT * NPIX];
__device__ float g_smax[L_TOT * NPIX];
__device__ float g_scale[L_TOT];
__device__ float g_shift[L_TOT];

// ---------------- helpers ----------------
__device__ __forceinline__ uint32_t smem_u32(const void* p) {
    uint32_t a;
    asm("{ .reg .u64 t; cvta.to.shared.u64 t, %1; cvt.u32.u64 %0, t; }" : "=r"(a) : "l"(p));
    return a;
}
__device__ __forceinline__ void ldsm4(uint32_t* r, uint32_t addr) {
    asm volatile("ldmatrix.sync.aligned.m8n8.x4.shared.b16 {%0,%1,%2,%3}, [%4];"
        : "=r"(r[0]), "=r"(r[1]), "=r"(r[2]), "=r"(r[3]) : "r"(addr));
}
__device__ __forceinline__ void mma16816(float* d, const uint32_t* a, const uint32_t* b) {
    asm volatile(
        "mma.sync.aligned.m16n8k16.row.col.f32.f16.f16.f32 "
        "{%0,%1,%2,%3}, {%4,%5,%6,%7}, {%8,%9}, {%0,%1,%2,%3};"
        : "+f"(d[0]), "+f"(d[1]), "+f"(d[2]), "+f"(d[3])
        : "r"(a[0]), "r"(a[1]), "r"(a[2]), "r"(a[3]), "r"(b[0]), "r"(b[1]));
}
#define CP_ASYNC16(dst, src) \
    asm volatile("cp.async.cg.shared.global [%0], [%1], 16;" \
        :: "r"((uint32_t)(dst)), "l"(src) : "memory")
#define CP_ASYNC16Z(dst, src, ssz) \
    asm volatile("cp.async.cg.shared.global [%0], [%1], 16, %2;" \
        :: "r"((uint32_t)(dst)), "l"(src), "r"(ssz) : "memory")
#define CP_COMMIT()  asm volatile("cp.async.commit_group;" ::: "memory")
#define CP_WAIT0()   asm volatile("cp.async.wait_group 0;" ::: "memory")
__device__ __forceinline__ unsigned long long ffma2(unsigned long long a,
                                                    unsigned long long b,
                                                    unsigned long long c) {
    unsigned long long d;
    asm("fma.rn.f32x2 %0, %1, %2, %3;" : "=l"(d) : "l"(a), "l"(b), "l"(c));
    return d;
}
__device__ __forceinline__ unsigned long long pack2(float lo, float hi) {
    unsigned long long d;
    asm("mov.b64 %0, {%1, %2};" : "=l"(d) : "f"(lo), "f"(hi));
    return d;
}
union U2F { unsigned long long u; float2 f; };

// ---------------- GEMM SMEM layout ----------------
#define ROW_B     272u                      // 128 fp16 = 256B + 16B pad
#define A_TILE_B  (128u * ROW_B)            // 34816
#define B_TILE_B  (64u * ROW_B)             // 17408
#define BUF_B     (A_TILE_B + B_TILE_B)     // 52224
#define OFF_S     (2u * BUF_B)
#define SMEM_GEMM (OFF_S + 9u * 64u * 4u)   // 106752

// ================= A prep =================
__global__ __launch_bounds__(256) void prep_a(const float* __restrict__ w) {
    int t = blockIdx.x * 256 + threadIdx.x;     // O_TOT*C_TOT
    int o = t >> 11, c = t & 2047;
    const float* src = w + (size_t)o * K_TOT + c * 9;
#pragma unroll
    for (int l = 0; l < 9; l++)
        g_a[(size_t)o * K_TOT + l * C_TOT + c] = __float2half_rn(src[l]);
}

// ================= x transpose: g_xt[p][c] = fp16(x[n,c,y,x]) =================
__global__ __launch_bounds__(256) void transpose_x(const float* __restrict__ x) {
    __shared__ float t[64][65];
    const int tid = threadIdx.x;
    const int p0 = blockIdx.x * 64;
    const int c0 = blockIdx.y * 64;
    const int pc = tid & 63;
    const int cr = tid >> 6;            // 0..3
    const int p = p0 + pc;
    const int n = p >> 10, hw = p & 1023;
    const float* xp = x + (((size_t)(n * C_TOT + c0)) << 10) + hw;
#pragma unroll
    for (int it = 0; it < 16; it++) {
        int c = cr + it * 4;
        t[c][pc] = xp[(size_t)c << 10];
    }
    __syncthreads();
#pragma unroll
    for (int it = 0; it < 16; it++) {
        int prow = cr + it * 4;
        g_xt[(size_t)(p0 + prow) * C_TOT + c0 + pc] = __float2half_rn(t[pc][prow]);
    }
}

// ================= conv path =================
__global__ __launch_bounds__(256) void transpose_cw(const float* __restrict__ cw) {
    int i = blockIdx.x * 256 + threadIdx.x;
    if (i < K_TOT * L_TOT) {
        int R = i / 9, j = i - R * 9;
        int l = R >> 11, c = R & 2047;
        g_cwt[i] = cw[(size_t)j * K_TOT + c * 9 + l];
    }
}

// grid (8, 72): 512-px tiles x (l, c-eighth). 256 threads, 2 px/thread (f32x2).
// Batched x loads (MLP=32/thread), 18KB smem -> ~4 CTAs/SM.
__global__ __launch_bounds__(256) void conv_partial(const float* __restrict__ x) {
    extern __shared__ char cvsm[];
    unsigned long long* cw2 = (unsigned long long*)cvsm;   // [CV_CCH*9] duplicated
    const int tid = threadIdx.x;
    const int p0  = blockIdx.x * 512;
    const int l   = blockIdx.y / CV_NCH;
    const int c0  = (blockIdx.y % CV_NCH) * CV_CCH;
    const int dy  = l / 3 - 1, dx = l % 3 - 1;

    const float* src = g_cwt + (size_t)(l * C_TOT + c0) * 9;
    for (int i = tid; i < CV_CCH * 9; i += 256) {
        float v = src[i];
        cw2[i] = pack2(v, v);
    }

    int pA = p0 + tid, pB = pA + 256;
    int nA = pA >> 10, remA = pA & 1023, yA = remA >> 5, xA = remA & 31;
    int nB = pB >> 10, remB = pB & 1023, yB = remB >> 5, xB = remB & 31;
    int yyA = yA + dy, xxA = xA + dx;
    int yyB = yB + dy, xxB = xB + dx;
    bool vA = ((unsigned)yyA < 32u) && ((unsigned)xxA < 32u);
    bool vB = ((unsigned)yyB < 32u) && ((unsigned)xxB < 32u);
    const float* ptrA = x + ((size_t)nA << 21) + ((size_t)c0 << 10) + (yyA << 5) + xxA;
    const float* ptrB = x + ((size_t)nB << 21) + ((size_t)c0 << 10) + (yyB << 5) + xxB;
    __syncthreads();

    unsigned long long acc[9];
#pragma unroll
    for (int j = 0; j < 9; j++) acc[j] = 0ULL;

    for (int cg = 0; cg < CV_CCH; cg += 16) {
        float va[16], vb[16];
#pragma unroll
        for (int t = 0; t < 16; t++) {
            size_t off = (size_t)(cg + t) << 10;
            va[t] = vA ? ptrA[off] : 0.f;
            vb[t] = vB ? ptrB[off] : 0.f;
        }
#pragma unroll
        for (int t = 0; t < 16; t++) {
            unsigned long long pk = pack2(va[t], vb[t]);
            const unsigned long long* wrow = cw2 + (cg + t) * 9;
#pragma unroll
            for (int j = 0; j < 9; j++)
                acc[j] = ffma2(pk, wrow[j], acc[j]);
        }
    }
    const size_t base = (size_t)blockIdx.y * (L_TOT * NPIX);
#pragma unroll
    for (int j = 0; j < 9; j++) {
        U2F u; u.u = acc[j];
        g_part[base + (size_t)j * NPIX + pA] = u.f.x;
        g_part[base + (size_t)j * NPIX + pB] = u.f.y;
    }
}

__global__ __launch_bounds__(256) void conv_reduce() {
    int i = blockIdx.x * 256 + threadIdx.x;
    if (i < L_TOT * NPIX) {
        float s = 0.f;
#pragma unroll
        for (int ch = 0; ch < CV_CHUNKS; ch++)
            s += g_part[(size_t)ch * (L_TOT * NPIX) + i];
        g_sigma[i] = s;
    }
}

__global__ __launch_bounds__(256) void bn_stats(const float* __restrict__ gamma,
                                                const float* __restrict__ beta) {
    __shared__ float shs[256], shq[256];
    const int j = blockIdx.x, tid = threadIdx.x;
    float s = 0.f, q = 0.f;
    for (int i = tid; i < NPIX; i += 256) {
        float v = g_sigma[j * NPIX + i];
        s += v; q += v * v;
    }
    shs[tid] = s; shq[tid] = q;
    __syncthreads();
    for (int st = 128; st > 0; st >>= 1) {
        if (tid < st) { shs[tid] += shs[tid + st]; shq[tid] += shq[tid + st]; }
        __syncthreads();
    }
    if (tid == 0) {
        float mean = shs[0] * (1.f / NPIX);
        float var  = shq[0] * (1.f / NPIX) - mean * mean;
        float inv  = rsqrtf(var + 1e-5f);
        float sc   = gamma[j] * inv;
        g_scale[j] = sc;
        g_shift[j] = beta[j] - mean * sc;
    }
}

__global__ __launch_bounds__(256) void softmax_k() {
    int p = blockIdx.x * 256 + threadIdx.x;
    float v[9];
    float m = -1e30f;
#pragma unroll
    for (int j = 0; j < 9; j++) {
        v[j] = g_sigma[j * NPIX + p] * g_scale[j] + g_shift[j];
        m = fmaxf(m, v[j]);
    }
    float s = 0.f;
#pragma unroll
    for (int j = 0; j < 9; j++) { v[j] = expf(v[j] - m); s += v[j]; }
    float inv = 1.f / s;
#pragma unroll
    for (int j = 0; j < 9; j++) g_smax[j * NPIX + p] = v[j] * inv;
}

// ================= main GEMM =================
// out[o,p] = sum_l s_l[p] * sum_c A[o][l*2048+c] * xt[p + off_l][c]
__global__ __launch_bounds__(256, 1) void gemm_mma(float* __restrict__ out) {
    extern __shared__ char smem_raw[];
    const uint32_t base = smem_u32(smem_raw);
    float* s_sh = (float*)(smem_raw + OFF_S);

    const int tid  = threadIdx.x;
    const int lane = tid & 31;
    const int wid  = tid >> 5;
    const int warp_m = wid & 3;
    const int warp_n = wid >> 2;
    const int p0     = blockIdx.x * N_TILE;
    const int o_base = blockIdx.y * M_TILE;
    const int n_img  = p0 >> 10;

    for (int i = tid; i < 9 * N_TILE; i += 256) {
        int l = i >> 6, pp = i & 63;
        s_sh[i] = g_smax[l * NPIX + p0 + pp];
    }
    __syncthreads();

    const int aRowT = tid >> 4;
    const int aC16  = tid & 15;
    const __half* ag = g_a + (size_t)(o_base + aRowT) * K_TOT + aC16 * 8;
    const int bRowT = tid >> 2;
    const int bC16  = tid & 3;
    const int pb = p0 + bRowT;
    const int yb = (pb & 1023) >> 5, xb = pb & 31;
    const __half* xt_row = g_xt + (size_t)pb * C_TOT + bC16 * 8;

    const uint32_t aRow  = (uint32_t)(warp_m * 32 + (lane & 15));
    const uint32_t aColB = (uint32_t)(((lane >> 4) & 1) * 16);
    const uint32_t bRow  = (uint32_t)(warp_n * 32 + ((lane >> 4) & 1) * 8 + (lane & 7));
    const uint32_t bColB = (uint32_t)(((lane >> 3) & 1) * 16);

    float fin[2][4][4], cur[2][4][4];
#pragma unroll
    for (int a = 0; a < 2; a++)
#pragma unroll
        for (int b = 0; b < 4; b++)
#pragma unroll
            for (int c = 0; c < 4; c++) { fin[a][b][c] = 0.f; cur[a][b][c] = 0.f; }

    auto CPA = [&](int kt, int buf) {
        uint32_t aB = base + (uint32_t)buf * BUF_B
                    + (uint32_t)aRowT * ROW_B + (uint32_t)aC16 * 16;
        const __half* ga = ag + (size_t)kt * K_CHUNK;
#pragma unroll
        for (int it = 0; it < 8; it++)
            CP_ASYNC16(aB + (uint32_t)it * 16u * ROW_B, ga + (size_t)it * 16 * K_TOT);
        int l  = kt >> 4;
        int dy = l / 3 - 1, dx = l - l / 3 * 3 - 1;
        bool v = ((unsigned)(yb + dy) < 32u) & ((unsigned)(xb + dx) < 32u);
        uint32_t ssz = v ? 16u : 0u;
        const __half* gb = v ? (xt_row + (ptrdiff_t)(dy * 32 + dx) * C_TOT) : g_xt;
        gb += (size_t)(kt & 15) * K_CHUNK;
        uint32_t bB = base + (uint32_t)buf * BUF_B + A_TILE_B
                    + (uint32_t)bRowT * ROW_B + (uint32_t)bC16 * 16;
#pragma unroll
        for (int it = 0; it < 4; it++)
            CP_ASYNC16Z(bB + (uint32_t)it * 64u, gb + (size_t)it * 32, ssz);
        CP_COMMIT();
    };

    auto COMPUTE = [&](int buf) {
        uint32_t aB = base + (uint32_t)buf * BUF_B;
        uint32_t bB = aB + A_TILE_B;
#pragma unroll
        for (int ks = 0; ks < 8; ks++) {
            uint32_t aF[2][4], bF[2][4];
#pragma unroll
            for (int ms = 0; ms < 2; ms++)
                ldsm4(aF[ms], aB + (aRow + ms * 16) * ROW_B + aColB + ks * 32);
#pragma unroll
            for (int np = 0; np < 2; np++)
                ldsm4(bF[np], bB + (bRow + np * 16) * ROW_B + bColB + ks * 32);
#pragma unroll
            for (int ms = 0; ms < 2; ms++)
#pragma unroll
                for (int ns = 0; ns < 4; ns++)
                    mma16816(cur[ms][ns], aF[ms], &bF[ns >> 1][(ns & 1) * 2]);
        }
    };

    CPA(0, 0);
    CP_WAIT0();
    __syncthreads();

    for (int lt = 0; lt < 9; lt++) {
#pragma unroll 1
        for (int ki = 0; ki < 16; ki++) {
            const int kt = lt * 16 + ki;
            const int buf = kt & 1;
            if (kt + 1 < NCHUNK) CPA(kt + 1, buf ^ 1);
            COMPUTE(buf);
            CP_WAIT0();
            __syncthreads();
        }
#pragma unroll
        for (int ns = 0; ns < 4; ns++) {
            int cn = warp_n * 32 + ns * 8 + (lane & 3) * 2;
            float s0 = s_sh[lt * 64 + cn];
            float s1 = s_sh[lt * 64 + cn + 1];
#pragma unroll
            for (int ms = 0; ms < 2; ms++) {
                fin[ms][ns][0] += cur[ms][ns][0] * s0;
                fin[ms][ns][1] += cur[ms][ns][1] * s1;
                fin[ms][ns][2] += cur[ms][ns][2] * s0;
                fin[ms][ns][3] += cur[ms][ns][3] * s1;
                cur[ms][ns][0] = 0.f; cur[ms][ns][1] = 0.f;
                cur[ms][ns][2] = 0.f; cur[ms][ns][3] = 0.f;
            }
        }
    }

    const int hw0 = (p0 & 1023);
#pragma unroll
    for (int ms = 0; ms < 2; ms++)
#pragma unroll
        for (int ns = 0; ns < 4; ns++) {
            int row  = o_base + warp_m * 32 + ms * 16 + (lane >> 2);
            int coln = hw0 + warp_n * 32 + ns * 8 + (lane & 3) * 2;
            float* p1 = out + (((size_t)(n_img * O_TOT + row)) << 10) + coln;
            *(float2*)p1 = make_float2(fin[ms][ns][0], fin[ms][ns][1]);
            float* p2 = p1 + ((size_t)8 << 10);
            *(float2*)p2 = make_float2(fin[ms][ns][2], fin[ms][ns][3]);
        }
}

// ---------------- launch ----------------
extern "C" void kernel_launch(void* const* d_in, const int* in_sizes, int n_in,
                              void* d_out, int out_size) {
    const float* x      = (const float*)d_in[0];
    const float* conv_w = (const float*)d_in[1];
    const float* gamma  = (const float*)d_in[2];
    const float* beta   = (const float*)d_in[3];
    const float* weight = (const float*)d_in[4];
    float* out = (float*)d_out;

    cudaFuncSetAttribute(gemm_mma, cudaFuncAttributeMaxDynamicSharedMemorySize, SMEM_GEMM);
    cudaFuncSetAttribute(conv_partial, cudaFuncAttributeMaxDynamicSharedMemorySize, CV_CCH * 9 * 8);

    prep_a      <<<(O_TOT * C_TOT) / 256, 256>>>(weight);
    transpose_x <<<dim3(NPIX / 64, C_TOT / 64), 256>>>(x);
    transpose_cw<<<(K_TOT * L_TOT + 255) / 256, 256>>>(conv_w);
    conv_partial<<<dim3(8, CV_CHUNKS), 256, CV_CCH * 9 * 8>>>(x);
    conv_reduce <<<(L_TOT * NPIX + 255) / 256, 256>>>();
    bn_stats    <<<9, 256>>>(gamma, beta);
    softmax_k   <<<NPIX / 256, 256>>>();
    gemm_mma    <<<dim3(NPIX / N_TILE, O_TOT / M_TILE), 256, SMEM_GEMM>>>(out);
}